// round 14
// baseline (speedup 1.0000x reference)
#include <cuda_runtime.h>
#include <cstdint>

#define M_   4096
#define B_   8
#define N_   512
#define FD_  128
#define BD_  128
#define H_   64
#define TMR  32
#define NTHR 512

__device__ float g_F[M_ * H_];        // (m, h)
__device__ float g_BF[B_ * H_ * N_];  // (b, h, n)

__device__ __forceinline__ void fma2(float2& d, const float2 a, const float2 b) {
    unsigned long long& dd = *reinterpret_cast<unsigned long long*>(&d);
    const unsigned long long aa = *reinterpret_cast<const unsigned long long*>(&a);
    const unsigned long long bb = *reinterpret_cast<const unsigned long long*>(&b);
    asm("fma.rn.f32x2 %0, %1, %2, %0;" : "+l"(dd) : "l"(aa), "l"(bb));
}
__device__ __forceinline__ float2 dup(float s) { return make_float2(s, s); }

__device__ __forceinline__ uint32_t f2tf(float f) {
    uint32_t u;
    asm("cvt.rna.tf32.f32 %0, %1;" : "=r"(u) : "f"(f));
    return u;
}
__device__ __forceinline__ void mma8(float* c, const uint32_t* a,
                                     uint32_t b0, uint32_t b1) {
    asm volatile(
        "mma.sync.aligned.m16n8k8.row.col.f32.tf32.tf32.f32 "
        "{%0,%1,%2,%3}, {%4,%5,%6,%7}, {%8,%9}, {%0,%1,%2,%3};"
        : "+f"(c[0]), "+f"(c[1]), "+f"(c[2]), "+f"(c[3])
        : "r"(a[0]), "r"(a[1]), "r"(a[2]), "r"(a[3]), "r"(b0), "r"(b1));
}

// ---------------- fused prep kernel (F + BF) -------------------------------
__global__ void __launch_bounds__(256) prep_all_kernel(
    const float* __restrict__ fin, const float* __restrict__ Wf,
    const float* __restrict__ bf,
    const float* __restrict__ bpre, const float* __restrict__ Wb,
    const float* __restrict__ bb)
{
    extern __shared__ float psm[];
    const int tid = threadIdx.x;
    const int bid = blockIdx.x;

    if (bid < 64) {
        float* WfT = psm;           // [d][h] stride 68
        float* FnT = psm + 8704;    // [d][r] stride 68
        const int m0 = bid * 64;
        for (int i = tid; i < 64 * 128; i += 256) {
            int h = i >> 7, d = i & 127;
            WfT[d * 68 + h] = Wf[i];
            FnT[d * 68 + h] = fin[(m0 + h) * FD_ + d];
        }
        __syncthreads();

        const int h0 = (tid & 15) * 4;
        const int r0 = (tid >> 4) * 4;
        float2 acc[4][2];
        #pragma unroll
        for (int i = 0; i < 4; i++) { acc[i][0] = dup(0.f); acc[i][1] = dup(0.f); }

        #pragma unroll 4
        for (int d = 0; d < 128; d++) {
            float4 w4 = *(const float4*)(WfT + d * 68 + h0);
            float4 f4 = *(const float4*)(FnT + d * 68 + r0);
            float2 wl = make_float2(w4.x, w4.y), wh = make_float2(w4.z, w4.w);
            fma2(acc[0][0], wl, dup(f4.x)); fma2(acc[0][1], wh, dup(f4.x));
            fma2(acc[1][0], wl, dup(f4.y)); fma2(acc[1][1], wh, dup(f4.y));
            fma2(acc[2][0], wl, dup(f4.z)); fma2(acc[2][1], wh, dup(f4.z));
            fma2(acc[3][0], wl, dup(f4.w)); fma2(acc[3][1], wh, dup(f4.w));
        }
        float4 bf4 = *(const float4*)(bf + h0);
        #pragma unroll
        for (int ri = 0; ri < 4; ri++) {
            float4 o = make_float4(acc[ri][0].x + bf4.x, acc[ri][0].y + bf4.y,
                                   acc[ri][1].x + bf4.z, acc[ri][1].y + bf4.w);
            *(float4*)(g_F + (m0 + r0 + ri) * H_ + h0) = o;
        }
    } else {
        float* WbT = psm;           // [d][h] stride 68
        float* bp  = psm + 8704;    // [d][nn] stride 64
        const int q  = bid - 64;
        const int b  = q >> 3;
        const int n0 = (q & 7) * 64;

        for (int i = tid; i < 64 * 128; i += 256) {
            int h = i >> 7, d = i & 127;
            WbT[d * 68 + h] = Wb[i];
        }
        for (int i = tid; i < 2048; i += 256) {
            int d = i >> 4, nn4 = (i & 15) << 2;
            *(float4*)(bp + d * 64 + nn4) =
                *(const float4*)(bpre + b * BD_ * N_ + d * N_ + n0 + nn4);
        }
        __syncthreads();

        const int h0  = (tid & 15) * 4;
        const int nn0 = (tid >> 4) * 4;
        float2 acc[4][2];
        #pragma unroll
        for (int i = 0; i < 4; i++) { acc[i][0] = dup(0.f); acc[i][1] = dup(0.f); }

        #pragma unroll 4
        for (int d = 0; d < 128; d++) {
            float4 w4 = *(const float4*)(WbT + d * 68 + h0);
            float4 v4 = *(const float4*)(bp + d * 64 + nn0);
            float2 vl = make_float2(v4.x, v4.y), vh = make_float2(v4.z, v4.w);
            fma2(acc[0][0], vl, dup(w4.x)); fma2(acc[0][1], vh, dup(w4.x));
            fma2(acc[1][0], vl, dup(w4.y)); fma2(acc[1][1], vh, dup(w4.y));
            fma2(acc[2][0], vl, dup(w4.z)); fma2(acc[2][1], vh, dup(w4.z));
            fma2(acc[3][0], vl, dup(w4.w)); fma2(acc[3][1], vh, dup(w4.w));
        }
        #pragma unroll
        for (int hi = 0; hi < 4; hi++) {
            float bbh = __ldg(bb + h0 + hi);
            float4 o = make_float4(acc[hi][0].x + bbh, acc[hi][0].y + bbh,
                                   acc[hi][1].x + bbh, acc[hi][1].y + bbh);
            *(float4*)(g_BF + b * H_ * N_ + (h0 + hi) * N_ + n0 + nn0) = o;
        }
    }
}

// ------------------------------- main --------------------------------------
// Pass 1: tf32 MMA, B-fragments loaded DIRECTLY from global into registers
// (double-buffered per 8-k chunk). No cp.async, no staging smem, no waits.
__global__ void __launch_bounds__(NTHR) main_kernel(
    const int* __restrict__ batch, const float* __restrict__ bvin,
    const float* __restrict__ Wbv, const float* __restrict__ bbv,
    const float* __restrict__ Wo, const float* __restrict__ bo,
    float* __restrict__ out)
{
    extern __shared__ float sm[];
    float* WoT   = sm;            // [k][j] stride 68 = 8704
    float* cat   = sm + 8704;     // 32x132 = 4224
    float* bvs   = sm + 12928;    // 6*520 = 3120
    float* Fk    = sm + 16048;    // [2][32][36] = 2304 (scaled by 0.125)
    float* red   = sm + 18352;    // [2][8][32] = 512
    float* rinv  = sm + 18864;    // 64
    float* ypart = sm + 18928;    // [2][8][32][3] = 3072
    float* yfin  = sm + 22000;    // [64][6] = 384
    __shared__ int bsh[TMR];

    const int tid = threadIdx.x;
    const int w = tid >> 5, l = tid & 31;
    const int m0 = blockIdx.x * TMR;

    const int bmin = __ldg(batch + m0);
    const int bmax = __ldg(batch + m0 + TMR - 1);
    const bool uni = (bmin == bmax);

    const int half = w >> 3;            // warps 0-7: e, 8-15: g
    const int wq   = w & 7;             // n-chunk of 64
    const int lq   = l >> 2;            // 0..7
    const int lm   = l & 3;             // 0..3

    if (tid < TMR) bsh[tid] = batch[m0 + tid];
    // Fk[half][r][k] stride 36
    #pragma unroll
    for (int s = 0; s < 4; s++) {
        int i = tid + s * 512;
        int hh = i >> 10, r = (i >> 5) & 31, k = i & 31;
        Fk[hh * 1152 + r * 36 + k] = g_F[(m0 + r) * H_ + hh * 32 + k] * 0.125f;
    }

    // B-fragment base for this lane (row = k-index, col = n)
    const float* gB = g_BF + (half * 32) * 512 + wq * 64 + lq;

    float c[2][8][4];
    #pragma unroll
    for (int mt = 0; mt < 2; mt++)
        #pragma unroll
        for (int nt = 0; nt < 8; nt++)
            #pragma unroll
            for (int q = 0; q < 4; q++) c[mt][nt][q] = 0.f;

    float vb[2][16];

#define LOADC(BUF, BC, S) do { \
        const float* p = gB + (size_t)(BC) * 32768 + ((S) * 8 + lm) * 512; \
        _Pragma("unroll") \
        for (int nt = 0; nt < 8; nt++) { \
            (BUF)[nt]     = __ldg(p + nt * 8); \
            (BUF)[8 + nt] = __ldg(p + 4 * 512 + nt * 8); \
        } \
    } while (0)

    // issue first chunk's loads before the Fk barrier (overlap)
    LOADC(vb[0], bmin, 0);
    __syncthreads();   // Fk visible

    // ---- stage WoT transpose + bv preload NOW (hidden under pass-1) -------
    for (int i = tid; i < 8192; i += NTHR) {
        int j = i >> 7, k = i & 127;
        WoT[k * 68 + j] = Wo[i];
    }
    if (uni) {
        for (int i = tid; i < 3072; i += NTHR) {
            int cc = i >> 9, n = i & 511;
            bvs[cc * 520 + n] = bvin[bmin * 6 * N_ + cc * N_ + n];
        }
    }

    const float* fbase = Fk + half * 1152 + lq * 36 + lm;

#define COMPC(BUF, S, MASKED, BC) do { \
        uint32_t Ax[2][4]; \
        _Pragma("unroll") \
        for (int mt = 0; mt < 2; mt++) { \
            const float* fb = fbase + mt * 16 * 36 + (S) * 8; \
            bool oklo = !(MASKED) || (bsh[lq + mt * 16] == (BC)); \
            bool okhi = !(MASKED) || (bsh[lq + 8 + mt * 16] == (BC)); \
            Ax[mt][0] = f2tf(oklo ? fb[0] : 0.f); \
            Ax[mt][1] = f2tf(okhi ? fb[8 * 36] : 0.f); \
            Ax[mt][2] = f2tf(oklo ? fb[4] : 0.f); \
            Ax[mt][3] = f2tf(okhi ? fb[8 * 36 + 4] : 0.f); \
        } \
        _Pragma("unroll") \
        for (int nt = 0; nt < 8; nt++) { \
            uint32_t b0 = f2tf((BUF)[nt]); \
            uint32_t b1 = f2tf((BUF)[8 + nt]); \
            mma8(c[0][nt], Ax[0], b0, b1); \
            mma8(c[1][nt], Ax[1], b0, b1); \
        } \
    } while (0)

    // =================== pass 1: tf32 MMA, direct-LDG B ====================
    if (uni) {
        LOADC(vb[1], bmin, 1);
        COMPC(vb[0], 0, false, 0);
        LOADC(vb[0], bmin, 2);
        COMPC(vb[1], 1, false, 0);
        LOADC(vb[1], bmin, 3);
        COMPC(vb[0], 2, false, 0);
        COMPC(vb[1], 3, false, 0);
    } else {
        for (int bc = bmin; bc <= bmax; bc++) {
            if (bc != bmin) LOADC(vb[0], bc, 0);
            LOADC(vb[1], bc, 1);
            COMPC(vb[0], 0, true, bc);
            LOADC(vb[0], bc, 2);
            COMPC(vb[1], 1, true, bc);
            LOADC(vb[1], bc, 3);
            COMPC(vb[0], 2, true, bc);
            COMPC(vb[1], 3, true, bc);
        }
    }

    // =================== softmax: exp + sum ================================
    float srow[4];
    #pragma unroll
    for (int j = 0; j < 4; j++) {
        const int mt = j >> 1, hi = (j & 1) * 2;
        float s = 0.f;
        #pragma unroll
        for (int nt = 0; nt < 8; nt++) {
            float e0 = __expf(c[mt][nt][hi]);
            float e1 = __expf(c[mt][nt][hi + 1]);
            c[mt][nt][hi] = e0; c[mt][nt][hi + 1] = e1;
            s += e0 + e1;
        }
        srow[j] = s;
    }
    #pragma unroll
    for (int off = 1; off <= 2; off <<= 1)
        #pragma unroll
        for (int j = 0; j < 4; j++)
            srow[j] += __shfl_xor_sync(0xffffffffu, srow[j], off);
    if (lm == 0)
        #pragma unroll
        for (int j = 0; j < 4; j++)
            red[half * 256 + wq * 32 + lq + (j & 1) * 8 + (j >> 1) * 16] = srow[j];
    __syncthreads();
    if (tid < 64) {
        int hh = tid >> 5, r = tid & 31;
        float s = 0.f;
        #pragma unroll
        for (int q = 0; q < 8; q++) s += red[hh * 256 + q * 32 + r];
        rinv[tid] = 1.f / s;
    }
    __syncthreads();

    // =================== pass 2: 6-dim trick ===============================
    #pragma unroll
    for (int cg = 0; cg < 2; cg++) {
        float2 y2[4][3];
        #pragma unroll
        for (int j = 0; j < 4; j++)
            #pragma unroll
            for (int cc = 0; cc < 3; cc++) y2[j][cc] = dup(0.f);

        for (int bc = bmin; bc <= bmax; bc++) {
            if (!uni) {
                __syncthreads();
                for (int i = tid; i < 1536; i += NTHR) {
                    int cc = i >> 9, n = i & 511;
                    bvs[cc * 520 + n] = bvin[bc * 6 * N_ + (cg * 3 + cc) * N_ + n];
                }
                __syncthreads();
            }
            const float* bvbase = uni ? (bvs + cg * 3 * 520) : bvs;

            bool msk[4];
            #pragma unroll
            for (int j = 0; j < 4; j++)
                msk[j] = uni || (bsh[lq + (j & 1) * 8 + (j >> 1) * 16] == bc);

            #pragma unroll
            for (int cc = 0; cc < 3; cc++) {
                const float* bp2 = bvbase + cc * 520 + wq * 64 + 2 * lm;
                #pragma unroll
                for (int nt = 0; nt < 8; nt++) {
                    float2 bv2 = *(const float2*)(bp2 + nt * 8);
                    #pragma unroll
                    for (int j = 0; j < 4; j++) {
                        if (msk[j]) {
                            const int mt = j >> 1, hi = (j & 1) * 2;
                            fma2(y2[j][cc],
                                 make_float2(c[mt][nt][hi], c[mt][nt][hi + 1]), bv2);
                        }
                    }
                }
            }
        }

        float yv[4][3];
        #pragma unroll
        for (int j = 0; j < 4; j++)
            #pragma unroll
            for (int cc = 0; cc < 3; cc++) yv[j][cc] = y2[j][cc].x + y2[j][cc].y;
        #pragma unroll
        for (int off = 1; off <= 2; off <<= 1)
            #pragma unroll
            for (int j = 0; j < 4; j++)
                #pragma unroll
                for (int cc = 0; cc < 3; cc++)
                    yv[j][cc] += __shfl_xor_sync(0xffffffffu, yv[j][cc], off);
        if (lm == 0)
            #pragma unroll
            for (int j = 0; j < 4; j++) {
                int r = lq + (j & 1) * 8 + (j >> 1) * 16;
                #pragma unroll
                for (int cc = 0; cc < 3; cc++)
                    ypart[((half * 8 + wq) * 32 + r) * 3 + cc] = yv[j][cc];
            }
        __syncthreads();
        if (tid < 192) {
            int hh = tid / 96, rem = tid % 96, rr = rem / 3, cc = rem % 3;
            float s = 0.f;
            #pragma unroll
            for (int q = 0; q < 8; q++)
                s += ypart[((hh * 8 + q) * 32 + rr) * 3 + cc];
            yfin[(hh * 32 + rr) * 6 + cg * 3 + cc] = s * rinv[hh * 32 + rr];
        }
        __syncthreads();
    }

    // =================== cat[r][h] = Wbv @ y + bbv =========================
    {
        int r = tid >> 4, hq = (tid & 15) * 4;
        #pragma unroll
        for (int hh = 0; hh < 4; hh++) {
            int h = hq + hh;
            float se = 0.f, sg = 0.f;
            #pragma unroll
            for (int cc = 0; cc < 6; cc++) {
                float wv = __ldg(Wbv + h * 6 + cc);
                se += wv * yfin[r * 6 + cc];
                sg += wv * yfin[(32 + r) * 6 + cc];
            }
            float bb2 = __ldg(bbv + h);
            cat[r * 132 + h]      = se + bb2;
            cat[r * 132 + 64 + h] = sg + bb2;
        }
    }
    __syncthreads();

    // =================== pass 3: out = cat @ Wo.T + bo =====================
    {
        const int j0 = (w & 1) * 32 + (l & 7) * 4;
        const int r  = (w >> 1) * 4 + (l >> 3);
        const float* cr = cat + r * 132;
        float2 olo = dup(0.f), ohi = dup(0.f);
        #pragma unroll 4
        for (int k4 = 0; k4 < 128; k4 += 4) {
            float4 c4 = *(const float4*)(cr + k4);
            const float cs[4] = {c4.x, c4.y, c4.z, c4.w};
            #pragma unroll
            for (int kk = 0; kk < 4; kk++) {
                float4 w4 = *(const float4*)(WoT + (k4 + kk) * 68 + j0);
                float2 cd = dup(cs[kk]);
                fma2(olo, make_float2(w4.x, w4.y), cd);
                fma2(ohi, make_float2(w4.z, w4.w), cd);
            }
        }
        float4 o = make_float4(olo.x + __ldg(bo + j0),     olo.y + __ldg(bo + j0 + 1),
                               ohi.x + __ldg(bo + j0 + 2), ohi.y + __ldg(bo + j0 + 3));
        *(float4*)(out + (m0 + r) * H_ + j0) = o;
    }
}

// ------------------------------ launch -------------------------------------
extern "C" void kernel_launch(void* const* d_in, const int* in_sizes, int n_in,
                              void* d_out, int out_size)
{
    const float* fin  = (const float*)d_in[0];
    const int*   batch= (const int*)  d_in[1];
    const float* bpre = (const float*)d_in[2];
    const float* bvin = (const float*)d_in[3];
    const float* Wf   = (const float*)d_in[4];
    const float* bf   = (const float*)d_in[5];
    const float* Wb   = (const float*)d_in[6];
    const float* bb   = (const float*)d_in[7];
    const float* Wbv  = (const float*)d_in[8];
    const float* bbv  = (const float*)d_in[9];
    const float* Wo   = (const float*)d_in[10];
    const float* bo   = (const float*)d_in[11];
    float* out = (float*)d_out;

    const int psm = 17408 * sizeof(float);    // 69.6 KB
    const int msm = 22384 * sizeof(float);    // 89.5 KB
    cudaFuncSetAttribute(prep_all_kernel, cudaFuncAttributeMaxDynamicSharedMemorySize, psm);
    cudaFuncSetAttribute(main_kernel, cudaFuncAttributeMaxDynamicSharedMemorySize, msm);

    prep_all_kernel<<<128, 256, psm>>>(fin, Wf, bf, bpre, Wb, bb);
    main_kernel<<<M_ / TMR, NTHR, msm>>>(batch, bvin, Wbv, bbv, Wo, bo, out);
}

// round 15
// speedup vs baseline: 1.6179x; 1.6179x over previous
#include <cuda_runtime.h>
#include <cstdint>

#define M_   4096
#define B_   8
#define N_   512
#define FD_  128
#define BD_  128
#define H_   64
#define TMR  32
#define NTHR 512
#define WST  72        // warp-stage row stride (8 mod 32 -> conflict-free B lds)

__device__ float g_F[M_ * H_];        // (m, h)
__device__ float g_BF[B_ * H_ * N_];  // (b, h, n)

__device__ __forceinline__ void fma2(float2& d, const float2 a, const float2 b) {
    unsigned long long& dd = *reinterpret_cast<unsigned long long*>(&d);
    const unsigned long long aa = *reinterpret_cast<const unsigned long long*>(&a);
    const unsigned long long bb = *reinterpret_cast<const unsigned long long*>(&b);
    asm("fma.rn.f32x2 %0, %1, %2, %0;" : "+l"(dd) : "l"(aa), "l"(bb));
}
__device__ __forceinline__ float2 dup(float s) { return make_float2(s, s); }

__device__ __forceinline__ uint32_t f2tf(float f) {
    uint32_t u;
    asm("cvt.rna.tf32.f32 %0, %1;" : "=r"(u) : "f"(f));
    return u;
}
__device__ __forceinline__ void mma8(float* c, const uint32_t* a,
                                     uint32_t b0, uint32_t b1) {
    asm volatile(
        "mma.sync.aligned.m16n8k8.row.col.f32.tf32.tf32.f32 "
        "{%0,%1,%2,%3}, {%4,%5,%6,%7}, {%8,%9}, {%0,%1,%2,%3};"
        : "+f"(c[0]), "+f"(c[1]), "+f"(c[2]), "+f"(c[3])
        : "r"(a[0]), "r"(a[1]), "r"(a[2]), "r"(a[3]), "r"(b0), "r"(b1));
}

__device__ __forceinline__ uint32_t saddr(const void* p) {
    return (uint32_t)__cvta_generic_to_shared(p);
}
__device__ __forceinline__ void cp16(uint32_t dst, const void* src) {
    asm volatile("cp.async.cg.shared.global [%0], [%1], 16;" :: "r"(dst), "l"(src));
}
#define CP_COMMIT() asm volatile("cp.async.commit_group;")
#define CPW(n)      asm volatile("cp.async.wait_group " #n ";")

// ---------------- prep: both GEMMs as tf32 MMA -----------------------------
// bid 0..63 : F[m0+64][64]  = fin(64x128) @ Wf^T(128x64)  + bf
// bid 64..127: BF[b][64][n0+64] = Wb(64x128) @ bpre[b](128x64-slice) + bb
// A smem [64][132] (132 % 32 == 4 -> A-frag conflict-free)
// B smem [128][72] (72 % 32 == 8  -> B-frag conflict-free)
__global__ void __launch_bounds__(256) prep_all_kernel(
    const float* __restrict__ fin, const float* __restrict__ Wf,
    const float* __restrict__ bf,
    const float* __restrict__ bpre, const float* __restrict__ Wb,
    const float* __restrict__ bb)
{
    extern __shared__ float psm[];
    float* Asm = psm;          // 64*132 = 8448
    float* Bsm = psm + 8448;   // 128*72 = 9216
    const int tid = threadIdx.x;
    const int bid = blockIdx.x;
    const int w = tid >> 5, l = tid & 31;
    const int lq = l >> 2, lm = l & 3;
    const bool isF = bid < 64;

    if (isF) {
        const int m0 = bid * 64;
        for (int i = tid; i < 2048; i += 256) {
            int r = i >> 5, d4 = (i & 31) * 4;
            *(float4*)(Asm + r * 132 + d4) = *(const float4*)(fin + (m0 + r) * FD_ + d4);
        }
        for (int i = tid; i < 8192; i += 256) {   // WfT[d][h]
            int h = i >> 7, d = i & 127;
            Bsm[d * 72 + h] = Wf[i];
        }
    } else {
        const int q = bid - 64;
        const int b = q >> 3;
        const int n0 = (q & 7) * 64;
        for (int i = tid; i < 2048; i += 256) {
            int h = i >> 5, d4 = (i & 31) * 4;
            *(float4*)(Asm + h * 132 + d4) = *(const float4*)(Wb + h * BD_ + d4);
        }
        for (int i = tid; i < 2048; i += 256) {
            int d = i >> 4, j4 = (i & 15) * 4;
            *(float4*)(Bsm + d * 72 + j4) =
                *(const float4*)(bpre + b * BD_ * N_ + d * N_ + n0 + j4);
        }
    }
    __syncthreads();

    // warp tile: mt = w&3 (16-row m-tile), n-tiles (w>>2)*4 .. +3 (8 cols each)
    const int mt  = w & 3;
    const int ng0 = (w >> 2) * 4;

    float c[4][4];
    #pragma unroll
    for (int t = 0; t < 4; t++)
        #pragma unroll
        for (int q2 = 0; q2 < 4; q2++) c[t][q2] = 0.f;

    const float* arow = Asm + (mt * 16 + lq) * 132 + lm;
    #pragma unroll
    for (int ks = 0; ks < 16; ks++) {
        uint32_t A4[4];
        A4[0] = f2tf(arow[ks * 8]);
        A4[1] = f2tf(arow[8 * 132 + ks * 8]);
        A4[2] = f2tf(arow[ks * 8 + 4]);
        A4[3] = f2tf(arow[8 * 132 + ks * 8 + 4]);
        #pragma unroll
        for (int t = 0; t < 4; t++) {
            const float* bp = Bsm + (ks * 8 + lm) * 72 + (ng0 + t) * 8 + lq;
            uint32_t b0 = f2tf(bp[0]);
            uint32_t b1 = f2tf(bp[4 * 72]);
            mma8(c[t], A4, b0, b1);
        }
    }

    if (isF) {
        const int m0 = bid * 64;
        const int r0 = m0 + mt * 16 + lq;
        #pragma unroll
        for (int t = 0; t < 4; t++) {
            int col = (ng0 + t) * 8 + 2 * lm;      // h
            float2 bf2 = *(const float2*)(bf + col);
            *(float2*)(g_F + r0 * H_ + col) =
                make_float2(c[t][0] + bf2.x, c[t][1] + bf2.y);
            *(float2*)(g_F + (r0 + 8) * H_ + col) =
                make_float2(c[t][2] + bf2.x, c[t][3] + bf2.y);
        }
    } else {
        const int q = bid - 64;
        const int b = q >> 3;
        const int n0 = (q & 7) * 64;
        const int h0 = mt * 16 + lq;
        const float bb0 = __ldg(bb + h0), bb1 = __ldg(bb + h0 + 8);
        #pragma unroll
        for (int t = 0; t < 4; t++) {
            int col = n0 + (ng0 + t) * 8 + 2 * lm; // n
            *(float2*)(g_BF + b * 32768 + h0 * 512 + col) =
                make_float2(c[t][0] + bb0, c[t][1] + bb0);
            *(float2*)(g_BF + b * 32768 + (h0 + 8) * 512 + col) =
                make_float2(c[t][2] + bb1, c[t][3] + bb1);
        }
    }
}

// ---------------- per-warp stage: 32k x 64n slice, 4 cp groups -------------
__device__ __forceinline__ void warp_stage(float* wb, const float* gsrc, int l) {
    #pragma unroll
    for (int s = 0; s < 4; s++) {
        #pragma unroll
        for (int t = 0; t < 4; t++) {
            int idx = l + t * 32;            // 0..127
            int row = idx >> 4;              // 0..7
            int col4 = (idx & 15) * 4;       // 0..60
            int rr = s * 8 + row;
            cp16(saddr(wb + rr * WST + col4), gsrc + rr * 512 + col4);
        }
        CP_COMMIT();
    }
}

// ------------------------------- main (R13, proven) ------------------------
__global__ void __launch_bounds__(NTHR) main_kernel(
    const int* __restrict__ batch, const float* __restrict__ bvin,
    const float* __restrict__ Wbv, const float* __restrict__ bbv,
    const float* __restrict__ Wo, const float* __restrict__ bo,
    float* __restrict__ out)
{
    extern __shared__ float sm[];
    float* wstage = sm;           // 16 warps x 32 x WST = 36864
    float* WoT   = sm;            // alias [0, 8704)     [k][j] stride 68
    float* cat   = sm + 9216;     // alias [9216, 13440) 32x132
    float* bvs   = sm + 36864;    // 6*520 = 3120
    float* Fk    = sm + 39984;    // [2][32][36] = 2304 (scaled by 0.125)
    float* red   = sm + 42288;    // [2][8][32] = 512
    float* rinv  = sm + 42800;    // 64
    float* ypart = sm + 42864;    // [2][8][32][3] = 3072
    float* yfin  = sm + 45936;    // [64][6] = 384
    __shared__ int bsh[TMR];

    const int tid = threadIdx.x;
    const int w = tid >> 5, l = tid & 31;
    const int m0 = blockIdx.x * TMR;

    const int bmin = __ldg(batch + m0);
    const int bmax = __ldg(batch + m0 + TMR - 1);
    const bool uni = (bmin == bmax);

    const int half = w >> 3;            // warps 0-7: e, 8-15: g
    const int wq   = w & 7;             // n-chunk of 64
    const int lq   = l >> 2;            // 0..7
    const int lm   = l & 3;             // 0..3

    float* wb = wstage + w * (32 * WST);

    // issue warp-private copies IMMEDIATELY (hidden under Fk staging)
    if (uni)
        warp_stage(wb, g_BF + bmin * (H_ * N_) + (half * 32) * 512 + wq * 64, l);

    if (tid < TMR) bsh[tid] = batch[m0 + tid];
    // Fk[half][r][k] stride 36
    #pragma unroll
    for (int s = 0; s < 4; s++) {
        int i = tid + s * 512;
        int hh = i >> 10, r = (i >> 5) & 31, k = i & 31;
        Fk[hh * 1152 + r * 36 + k] = g_F[(m0 + r) * H_ + hh * 32 + k] * 0.125f;
    }
    __syncthreads();

    float c[2][8][4];
    #pragma unroll
    for (int mt = 0; mt < 2; mt++)
        #pragma unroll
        for (int nt = 0; nt < 8; nt++)
            #pragma unroll
            for (int q = 0; q < 4; q++) c[mt][nt][q] = 0.f;

    uint32_t A[4][2][4];
    const float* fbase = Fk + half * 1152 + lq * 36 + lm;

#define MMA_CHUNK(S) do { \
        const float* tb = wb + ((S) * 8 + lm) * WST + lq; \
        _Pragma("unroll") \
        for (int nt = 0; nt < 8; nt++) { \
            uint32_t b0 = f2tf(tb[nt * 8]); \
            uint32_t b1 = f2tf(tb[4 * WST + nt * 8]); \
            mma8(c[0][nt], A[S][0], b0, b1); \
            mma8(c[1][nt], A[S][1], b0, b1); \
        } \
    } while (0)

    // =================== pass 1: tf32 MMA, warp-private ====================
    if (uni) {
        #pragma unroll
        for (int s = 0; s < 4; s++)
            #pragma unroll
            for (int mt = 0; mt < 2; mt++) {
                const float* fb = fbase + mt * 16 * 36 + s * 8;
                A[s][mt][0] = f2tf(fb[0]);
                A[s][mt][1] = f2tf(fb[8 * 36]);
                A[s][mt][2] = f2tf(fb[4]);
                A[s][mt][3] = f2tf(fb[8 * 36 + 4]);
            }
        CPW(3); __syncwarp(); MMA_CHUNK(0);
        CPW(2); __syncwarp(); MMA_CHUNK(1);
        CPW(1); __syncwarp(); MMA_CHUNK(2);
        CPW(0); __syncwarp(); MMA_CHUNK(3);
    } else {
        for (int bc = bmin; bc <= bmax; bc++) {
            warp_stage(wb, g_BF + bc * (H_ * N_) + (half * 32) * 512 + wq * 64, l);
            #pragma unroll
            for (int s = 0; s < 4; s++)
                #pragma unroll
                for (int mt = 0; mt < 2; mt++) {
                    const float* fb = fbase + mt * 16 * 36 + s * 8;
                    bool oklo = (bsh[lq + mt * 16] == bc);
                    bool okhi = (bsh[lq + 8 + mt * 16] == bc);
                    A[s][mt][0] = f2tf(oklo ? fb[0] : 0.f);
                    A[s][mt][1] = f2tf(okhi ? fb[8 * 36] : 0.f);
                    A[s][mt][2] = f2tf(oklo ? fb[4] : 0.f);
                    A[s][mt][3] = f2tf(okhi ? fb[8 * 36 + 4] : 0.f);
                }
            CPW(3); __syncwarp(); MMA_CHUNK(0);
            CPW(2); __syncwarp(); MMA_CHUNK(1);
            CPW(1); __syncwarp(); MMA_CHUNK(2);
            CPW(0); __syncwarp(); MMA_CHUNK(3);
        }
    }
    __syncthreads();   // all pass-1 wstage reads done before WoT/cat alias

    // ---- stage WoT (transpose) + bv preload; overlaps softmax -------------
    for (int i = tid; i < 8192; i += NTHR) {
        int j = i >> 7, k = i & 127;
        WoT[k * 68 + j] = Wo[i];
    }
    if (uni) {
        for (int i = tid; i < 3072; i += NTHR) {
            int cc = i >> 9, n = i & 511;
            bvs[cc * 520 + n] = bvin[bmin * 6 * N_ + cc * N_ + n];
        }
    }

    // =================== softmax: exp + sum ================================
    float srow[4];
    #pragma unroll
    for (int j = 0; j < 4; j++) {
        const int mt = j >> 1, hi = (j & 1) * 2;
        float s = 0.f;
        #pragma unroll
        for (int nt = 0; nt < 8; nt++) {
            float e0 = __expf(c[mt][nt][hi]);
            float e1 = __expf(c[mt][nt][hi + 1]);
            c[mt][nt][hi] = e0; c[mt][nt][hi + 1] = e1;
            s += e0 + e1;
        }
        srow[j] = s;
    }
    #pragma unroll
    for (int off = 1; off <= 2; off <<= 1)
        #pragma unroll
        for (int j = 0; j < 4; j++)
            srow[j] += __shfl_xor_sync(0xffffffffu, srow[j], off);
    if (lm == 0)
        #pragma unroll
        for (int j = 0; j < 4; j++)
            red[half * 256 + wq * 32 + lq + (j & 1) * 8 + (j >> 1) * 16] = srow[j];
    __syncthreads();
    if (tid < 64) {
        int hh = tid >> 5, r = tid & 31;
        float s = 0.f;
        #pragma unroll
        for (int q = 0; q < 8; q++) s += red[hh * 256 + q * 32 + r];
        rinv[tid] = 1.f / s;
    }
    __syncthreads();

    // =================== pass 2: 6-dim trick ===============================
    #pragma unroll
    for (int cg = 0; cg < 2; cg++) {
        float2 y2[4][3];
        #pragma unroll
        for (int j = 0; j < 4; j++)
            #pragma unroll
            for (int cc = 0; cc < 3; cc++) y2[j][cc] = dup(0.f);

        for (int bc = bmin; bc <= bmax; bc++) {
            if (!uni) {
                __syncthreads();
                for (int i = tid; i < 1536; i += NTHR) {
                    int cc = i >> 9, n = i & 511;
                    bvs[cc * 520 + n] = bvin[bc * 6 * N_ + (cg * 3 + cc) * N_ + n];
                }
                __syncthreads();
            }
            const float* bvbase = uni ? (bvs + cg * 3 * 520) : bvs;

            bool msk[4];
            #pragma unroll
            for (int j = 0; j < 4; j++)
                msk[j] = uni || (bsh[lq + (j & 1) * 8 + (j >> 1) * 16] == bc);

            #pragma unroll
            for (int cc = 0; cc < 3; cc++) {
                const float* bp2 = bvbase + cc * 520 + wq * 64 + 2 * lm;
                #pragma unroll
                for (int nt = 0; nt < 8; nt++) {
                    float2 bv2 = *(const float2*)(bp2 + nt * 8);
                    #pragma unroll
                    for (int j = 0; j < 4; j++) {
                        if (msk[j]) {
                            const int mt = j >> 1, hi = (j & 1) * 2;
                            fma2(y2[j][cc],
                                 make_float2(c[mt][nt][hi], c[mt][nt][hi + 1]), bv2);
                        }
                    }
                }
            }
        }

        float yv[4][3];
        #pragma unroll
        for (int j = 0; j < 4; j++)
            #pragma unroll
            for (int cc = 0; cc < 3; cc++) yv[j][cc] = y2[j][cc].x + y2[j][cc].y;
        #pragma unroll
        for (int off = 1; off <= 2; off <<= 1)
            #pragma unroll
            for (int j = 0; j < 4; j++)
                #pragma unroll
                for (int cc = 0; cc < 3; cc++)
                    yv[j][cc] += __shfl_xor_sync(0xffffffffu, yv[j][cc], off);
        if (lm == 0)
            #pragma unroll
            for (int j = 0; j < 4; j++) {
                int r = lq + (j & 1) * 8 + (j >> 1) * 16;
                #pragma unroll
                for (int cc = 0; cc < 3; cc++)
                    ypart[((half * 8 + wq) * 32 + r) * 3 + cc] = yv[j][cc];
            }
        __syncthreads();
        if (tid < 192) {
            int hh = tid / 96, rem = tid % 96, rr = rem / 3, cc = rem % 3;
            float s = 0.f;
            #pragma unroll
            for (int q = 0; q < 8; q++)
                s += ypart[((hh * 8 + q) * 32 + rr) * 3 + cc];
            yfin[(hh * 32 + rr) * 6 + cg * 3 + cc] = s * rinv[hh * 32 + rr];
        }
        __syncthreads();
    }

    // =================== cat[r][h] = Wbv @ y + bbv =========================
    {
        int r = tid >> 4, hq = (tid & 15) * 4;
        #pragma unroll
        for (int hh = 0; hh < 4; hh++) {
            int h = hq + hh;
            float se = 0.f, sg = 0.f;
            #pragma unroll
            for (int cc = 0; cc < 6; cc++) {
                float wv = __ldg(Wbv + h * 6 + cc);
                se += wv * yfin[r * 6 + cc];
                sg += wv * yfin[(32 + r) * 6 + cc];
            }
            float bb2 = __ldg(bbv + h);
            cat[r * 132 + h]      = se + bb2;
            cat[r * 132 + 64 + h] = sg + bb2;
        }
    }
    __syncthreads();

    // =================== pass 3: out = cat @ Wo.T + bo =====================
    {
        const int j0 = (w & 1) * 32 + (l & 7) * 4;
        const int r  = (w >> 1) * 4 + (l >> 3);
        const float* cr = cat + r * 132;
        float2 olo = dup(0.f), ohi = dup(0.f);
        #pragma unroll 4
        for (int k4 = 0; k4 < 128; k4 += 4) {
            float4 c4 = *(const float4*)(cr + k4);
            const float cs[4] = {c4.x, c4.y, c4.z, c4.w};
            #pragma unroll
            for (int kk = 0; kk < 4; kk++) {
                float4 w4 = *(const float4*)(WoT + (k4 + kk) * 68 + j0);
                float2 cd = dup(cs[kk]);
                fma2(olo, make_float2(w4.x, w4.y), cd);
                fma2(ohi, make_float2(w4.z, w4.w), cd);
            }
        }
        float4 o = make_float4(olo.x + __ldg(bo + j0),     olo.y + __ldg(bo + j0 + 1),
                               ohi.x + __ldg(bo + j0 + 2), ohi.y + __ldg(bo + j0 + 3));
        *(float4*)(out + (m0 + r) * H_ + j0) = o;
    }
}

// ------------------------------ launch -------------------------------------
extern "C" void kernel_launch(void* const* d_in, const int* in_sizes, int n_in,
                              void* d_out, int out_size)
{
    const float* fin  = (const float*)d_in[0];
    const int*   batch= (const int*)  d_in[1];
    const float* bpre = (const float*)d_in[2];
    const float* bvin = (const float*)d_in[3];
    const float* Wf   = (const float*)d_in[4];
    const float* bf   = (const float*)d_in[5];
    const float* Wb   = (const float*)d_in[6];
    const float* bb   = (const float*)d_in[7];
    const float* Wbv  = (const float*)d_in[8];
    const float* bbv  = (const float*)d_in[9];
    const float* Wo   = (const float*)d_in[10];
    const float* bo   = (const float*)d_in[11];
    float* out = (float*)d_out;

    const int psm = 17664 * sizeof(float);    // 70.7 KB
    const int msm = 46320 * sizeof(float);    // 185.3 KB
    cudaFuncSetAttribute(prep_all_kernel, cudaFuncAttributeMaxDynamicSharedMemorySize, psm);
    cudaFuncSetAttribute(main_kernel, cudaFuncAttributeMaxDynamicSharedMemorySize, msm);

    prep_all_kernel<<<128, 256, psm>>>(fin, Wf, bf, bpre, Wb, bb);
    main_kernel<<<M_ / TMR, NTHR, msm>>>(batch, bvin, Wbv, bbv, Wo, bo, out);
}